// round 12
// baseline (speedup 1.0000x reference)
#include <cuda_runtime.h>

#define NN 50000
#define EE 800000
#define ET 850000   // EE + NN self loops
#define CAP 96      // padded adjacency capacity (deg ~ Poisson(16)+1; P(>95) ~ 0)

// ---------------- scratch (static device globals; no allocation) ----------------
__device__ __align__(16) float g_xl[NN * 128];
__device__ __align__(16) float g_xr[NN * 128];
__device__ __align__(16) float g_ha[NN * 128];
__device__ __align__(16) float g_hb[NN * 128];
__device__ int   g_cnt[NN];          // per-node cursor / degree
__device__ int   g_adj[NN * CAP];    // padded adjacency (src lists by dst)
// concatenated padded weights: L0 [32][256] @0, L1 [128][256] @8192, L2 [128][64] @40960
__device__ __align__(16) float g_wcat[49152];

#define OFF_WC0 0
#define OFF_WC1 8192
#define OFF_WC2 40960

// ---------------- weight repack: Wcat = [Wl | Wr], K zero-padded ----------------
__global__ void k_repack(const float* __restrict__ W0l, const float* __restrict__ W0r,
                         const float* __restrict__ W1l, const float* __restrict__ W1r,
                         const float* __restrict__ W2l, const float* __restrict__ W2r) {
    int i = blockIdx.x * blockDim.x + threadIdx.x;
    if (i >= 49152) return;
    float v = 0.f;
    if (i < 8192) {                       // L0: KPAD=32, MCAT=256, KREAL=18
        int k = i >> 8, c = i & 255;
        if (k < 18) v = (c < 128) ? W0l[k * 128 + c] : W0r[k * 128 + (c - 128)];
        g_wcat[OFF_WC0 + i] = v;
    } else if (i < 40960) {               // L1: K=128, MCAT=256
        int j = i - 8192;
        int k = j >> 8, c = j & 255;
        v = (c < 128) ? W1l[k * 128 + c] : W1r[k * 128 + (c - 128)];
        g_wcat[i] = v;
    } else {                              // L2: K=128, MCAT=64
        int j = i - 40960;
        int k = j >> 6, c = j & 63;
        v = (c < 32) ? W2l[k * 32 + c] : W2r[k * 32 + (c - 32)];
        g_wcat[i] = v;
    }
}

// ---------------- padded CSR build (by dst): memset + single scatter ----------------
__global__ void k_scatter_pad(const int* __restrict__ ei) {
    int e = blockIdx.x * blockDim.x + threadIdx.x;
    if (e >= ET) return;
    int src, dst;
    if (e < EE) { src = ei[e]; dst = ei[EE + e]; }
    else        { src = e - EE; dst = e - EE; }
    int pos = atomicAdd(&g_cnt[dst], 1);
    if (pos < CAP) g_adj[dst * CAP + pos] = src;
}

// ---------------- raw tf32 mma helpers ----------------
__device__ __forceinline__ unsigned f2tf(float v) {
    unsigned u; asm("cvt.rna.tf32.f32 %0, %1;" : "=r"(u) : "f"(v)); return u;
}
__device__ __forceinline__ void mma_tf32(float* c, const unsigned* a, const unsigned* b) {
    asm("mma.sync.aligned.m16n8k8.row.col.f32.tf32.tf32.f32 "
        "{%0,%1,%2,%3},{%4,%5,%6,%7},{%8,%9},{%0,%1,%2,%3};"
        : "+f"(c[0]), "+f"(c[1]), "+f"(c[2]), "+f"(c[3])
        : "r"(a[0]), "r"(a[1]), "r"(a[2]), "r"(a[3]), "r"(b[0]), "r"(b[1]));
}

// ---------------- smem-free tf32 mma dual GEMM ----------------
template<int KREAL, int KPAD, int MCAT, int MOUT>
__global__ void k_linm(const float* __restrict__ in, const float* __restrict__ W,
                       const float* __restrict__ b1, const float* __restrict__ b2,
                       float* __restrict__ out1, float* __restrict__ out2, int nrows) {
    int tid  = threadIdx.x;
    int lane = tid & 31;
    int wid  = tid >> 5;
    int gid  = lane >> 2;      // group id 0..7
    int tig  = lane & 3;       // thread in group 0..3

    int wcol = wid & 1, wrow = wid >> 1;
    int rbase = blockIdx.x * 128 + wrow * 32;
    int cbase = blockIdx.y * 64 + wcol * 32;

    float acc[2][4][4];
#pragma unroll
    for (int mi = 0; mi < 2; mi++)
#pragma unroll
        for (int ni = 0; ni < 4; ni++)
#pragma unroll
            for (int q = 0; q < 4; q++) acc[mi][ni][q] = 0.f;

    int rA[2]; bool okA[2], okA8[2];
#pragma unroll
    for (int mi = 0; mi < 2; mi++) {
        rA[mi] = rbase + mi * 16 + gid;
        okA[mi]  = rA[mi] < nrows;
        okA8[mi] = rA[mi] + 8 < nrows;
    }

    for (int kc = 0; kc < KPAD; kc += 8) {
        int c0 = kc + tig, c1 = kc + tig + 4;
        bool kc0 = (KREAL >= KPAD) || (c0 < KREAL);
        bool kc1 = (KREAL >= KPAD) || (c1 < KREAL);

        unsigned A[2][4];
#pragma unroll
        for (int mi = 0; mi < 2; mi++) {
            const float* p0 = in + (long)rA[mi] * KREAL;
            const float* p1 = p0 + 8L * KREAL;
            A[mi][0] = f2tf((okA[mi]  && kc0) ? __ldg(p0 + c0) : 0.f);
            A[mi][1] = f2tf((okA8[mi] && kc0) ? __ldg(p1 + c0) : 0.f);
            A[mi][2] = f2tf((okA[mi]  && kc1) ? __ldg(p0 + c1) : 0.f);
            A[mi][3] = f2tf((okA8[mi] && kc1) ? __ldg(p1 + c1) : 0.f);
        }
        unsigned B[4][2];
#pragma unroll
        for (int ni = 0; ni < 4; ni++) {
            int bcol = cbase + ni * 8 + gid;
            B[ni][0] = f2tf(__ldg(W + (long)c0 * MCAT + bcol));
            B[ni][1] = f2tf(__ldg(W + (long)c1 * MCAT + bcol));
        }
#pragma unroll
        for (int mi = 0; mi < 2; mi++)
#pragma unroll
            for (int ni = 0; ni < 4; ni++)
                mma_tf32(acc[mi][ni], A[mi], B[ni]);
    }

#pragma unroll
    for (int mi = 0; mi < 2; mi++) {
#pragma unroll
        for (int ni = 0; ni < 4; ni++) {
            int col = cbase + ni * 8 + tig * 2;
#pragma unroll
            for (int h = 0; h < 2; h++) {
                int row = rA[mi] + h * 8;
                if (row >= nrows) continue;
                float vx = acc[mi][ni][h * 2], vy = acc[mi][ni][h * 2 + 1];
                if (col < MOUT) {
                    float2 bb = *(const float2*)(b1 + col);
                    *(float2*)(out1 + (long)row * MOUT + col) =
                        make_float2(vx + bb.x, vy + bb.y);
                } else {
                    float2 bb = *(const float2*)(b2 + col - MOUT);
                    *(float2*)(out2 + (long)row * MOUT + col - MOUT) =
                        make_float2(vx + bb.x, vy + bb.y);
                }
            }
        }
    }
}

// ---------------- warp helpers ----------------
__device__ __forceinline__ float warp_sum(float v) {
#pragma unroll
    for (int o = 16; o > 0; o >>= 1) v += __shfl_xor_sync(0xffffffffu, v, o);
    return v;
}

// ---------------- fused GATv2 layer (HD=128, H=4) ----------------
// batch-of-4 edge processing: 4 independent gather+logit chains, zero buffer MOVs.
template<bool RES>
__global__ void __launch_bounds__(256, 6)
k_gat128(const float* __restrict__ xl, const float* __restrict__ xr,
         const float* __restrict__ att,
         const float* __restrict__ bo, const float* __restrict__ gg,
         const float* __restrict__ be, const float* __restrict__ resid,
         float* __restrict__ out) {
    int node = (blockIdx.x * blockDim.x + threadIdx.x) >> 5;
    int lane = threadIdx.x & 31;
    if (node >= NN) return;
    int deg = g_cnt[node];
    const int* adj = g_adj + (long)node * CAP;

    float4 xr4 = *(const float4*)(xr + (long)node * 128 + (lane << 2));
    float4 at4 = __ldg((const float4*)(att + (lane << 2)));

    float den = 0.f;
    float ax = 0.f, ay = 0.f, az = 0.f, aw = 0.f;

#define GAT_EDGE(V) do {                                                       \
        float t0 = (V).x + xr4.x; t0 = fmaxf(t0, 0.2f * t0);                   \
        float t1 = (V).y + xr4.y; t1 = fmaxf(t1, 0.2f * t1);                   \
        float t2 = (V).z + xr4.z; t2 = fmaxf(t2, 0.2f * t2);                   \
        float t3 = (V).w + xr4.w; t3 = fmaxf(t3, 0.2f * t3);                   \
        float p = fmaf(t0, at4.x, fmaf(t1, at4.y, fmaf(t2, at4.z, t3 * at4.w)));\
        p += __shfl_xor_sync(0xffffffffu, p, 1);                               \
        p += __shfl_xor_sync(0xffffffffu, p, 2);                               \
        p += __shfl_xor_sync(0xffffffffu, p, 4);                               \
        float a = __expf(fminf(p, 60.f));                                      \
        ax = fmaf(a, (V).x, ax); ay = fmaf(a, (V).y, ay);                      \
        az = fmaf(a, (V).z, az); aw = fmaf(a, (V).w, aw);                      \
        den += a;                                                              \
    } while (0)

    for (int base = 0; base < deg; base += 32) {
        int rem = deg - base;
        int n = rem > 32 ? 32 : rem;
        int s = adj[base + ((lane < n) ? lane : 0)];
        int j = 0;
        for (; j + 4 <= n; j += 4) {
            int s0 = __shfl_sync(0xffffffffu, s, j);
            int s1 = __shfl_sync(0xffffffffu, s, j + 1);
            int s2 = __shfl_sync(0xffffffffu, s, j + 2);
            int s3 = __shfl_sync(0xffffffffu, s, j + 3);
            float4 v0 = *(const float4*)(xl + (long)s0 * 128 + (lane << 2));
            float4 v1 = *(const float4*)(xl + (long)s1 * 128 + (lane << 2));
            float4 v2 = *(const float4*)(xl + (long)s2 * 128 + (lane << 2));
            float4 v3 = *(const float4*)(xl + (long)s3 * 128 + (lane << 2));
            GAT_EDGE(v0);
            GAT_EDGE(v1);
            GAT_EDGE(v2);
            GAT_EDGE(v3);
        }
        for (; j < n; j++) {
            int ss = __shfl_sync(0xffffffffu, s, j);
            float4 v = *(const float4*)(xl + (long)ss * 128 + (lane << 2));
            GAT_EDGE(v);
        }
    }
#undef GAT_EDGE

    float inv = 1.f / den;
    float4 bo4 = __ldg((const float4*)(bo + (lane << 2)));
    float o0 = ax * inv + bo4.x;
    float o1 = ay * inv + bo4.y;
    float o2 = az * inv + bo4.z;
    float o3 = aw * inv + bo4.w;

    float mean = warp_sum(o0 + o1 + o2 + o3) * (1.f / 128.f);
    float e0 = o0 - mean, e1 = o1 - mean, e2 = o2 - mean, e3 = o3 - mean;
    float var = warp_sum(e0 * e0 + e1 * e1 + e2 * e2 + e3 * e3) * (1.f / 128.f);
    float rinv = rsqrtf(var + 1e-5f);
    float4 g4  = __ldg((const float4*)(gg + (lane << 2)));
    float4 be4 = __ldg((const float4*)(be + (lane << 2)));
    float v0 = e0 * rinv * g4.x + be4.x;
    float v1 = e1 * rinv * g4.y + be4.y;
    float v2 = e2 * rinv * g4.z + be4.z;
    float v3 = e3 * rinv * g4.w + be4.w;
    v0 = (v0 > 0.f) ? v0 : (__expf(v0) - 1.f);
    v1 = (v1 > 0.f) ? v1 : (__expf(v1) - 1.f);
    v2 = (v2 > 0.f) ? v2 : (__expf(v2) - 1.f);
    v3 = (v3 > 0.f) ? v3 : (__expf(v3) - 1.f);
    if (RES) {
        float4 r4 = *(const float4*)(resid + (long)node * 128 + (lane << 2));
        v0 += r4.x; v1 += r4.y; v2 += r4.z; v3 += r4.w;
    }
    *(float4*)(out + (long)node * 128 + (lane << 2)) = make_float4(v0, v1, v2, v3);
}

// ---------------- layer-2 (HD=32, H=1) fused with final MLP ----------------
__global__ void __launch_bounds__(256, 6)
k_gat_final(const float* __restrict__ xl, const float* __restrict__ xr,
            const float* __restrict__ att,
            const float* __restrict__ bo, const float* __restrict__ gg,
            const float* __restrict__ be,
            const float* __restrict__ cW1, const float* __restrict__ cb1,
            const float* __restrict__ cW2, const float* __restrict__ cb2,
            float* __restrict__ out) {
    __shared__ float sh[8][32];
    int node = (blockIdx.x * blockDim.x + threadIdx.x) >> 5;
    int lane = threadIdx.x & 31;
    int wib  = threadIdx.x >> 5;
    if (node >= NN) return;
    int deg = g_cnt[node];
    const int* adj = g_adj + (long)node * CAP;

    float xrv = xr[(long)node * 32 + lane];
    float atv = __ldg(&att[lane]);

#define FIN_EDGE(V) do {                                                       \
        float t = (V) + xrv; t = fmaxf(t, 0.2f * t);                           \
        float p = warp_sum(t * atv);                                           \
        float a = __expf(fminf(p, 60.f));                                      \
        acc = fmaf(a, (V), acc);                                               \
        den += a;                                                              \
    } while (0)

    float den = 0.f, acc = 0.f;
    for (int base = 0; base < deg; base += 32) {
        int rem = deg - base;
        int n = rem > 32 ? 32 : rem;
        int s = adj[base + ((lane < n) ? lane : 0)];
        int j = 0;
        for (; j + 4 <= n; j += 4) {
            int s0 = __shfl_sync(0xffffffffu, s, j);
            int s1 = __shfl_sync(0xffffffffu, s, j + 1);
            int s2 = __shfl_sync(0xffffffffu, s, j + 2);
            int s3 = __shfl_sync(0xffffffffu, s, j + 3);
            float v0 = xl[(long)s0 * 32 + lane];
            float v1 = xl[(long)s1 * 32 + lane];
            float v2 = xl[(long)s2 * 32 + lane];
            float v3 = xl[(long)s3 * 32 + lane];
            FIN_EDGE(v0);
            FIN_EDGE(v1);
            FIN_EDGE(v2);
            FIN_EDGE(v3);
        }
        for (; j < n; j++) {
            int ss = __shfl_sync(0xffffffffu, s, j);
            float v = xl[(long)ss * 32 + lane];
            FIN_EDGE(v);
        }
    }
#undef FIN_EDGE
    float o = acc / den + bo[lane];

    float mean = warp_sum(o) * (1.f / 32.f);
    float ec = o - mean;
    float var = warp_sum(ec * ec) * (1.f / 32.f);
    float v = ec * rsqrtf(var + 1e-5f) * gg[lane] + be[lane];
    v = (v > 0.f) ? v : (__expf(v) - 1.f);   // ELU

    sh[wib][lane] = v;
    __syncwarp();

    float r = 0.f;
    if (lane < 16) {
        float c = cb1[lane];
#pragma unroll
        for (int j = 0; j < 32; j++) c += sh[wib][j] * cW1[j * 16 + lane];
        c = (c > 0.f) ? c : (__expf(c) - 1.f);   // ELU
        r = c * cW2[lane];
    }
#pragma unroll
    for (int o2 = 8; o2 > 0; o2 >>= 1) r += __shfl_xor_sync(0xffffffffu, r, o2);
    if (lane == 0) out[node] = r + cb2[0];
}

// ---------------- host ----------------
extern "C" void kernel_launch(void* const* d_in, const int* in_sizes, int n_in,
                              void* d_out, int out_size) {
    const float* x    = (const float*)d_in[0];
    const int*   ei   = (const int*)  d_in[1];
    const float* Wl0  = (const float*)d_in[2];  const float* bl0 = (const float*)d_in[3];
    const float* Wr0  = (const float*)d_in[4];  const float* br0 = (const float*)d_in[5];
    const float* att0 = (const float*)d_in[6];  const float* bo0 = (const float*)d_in[7];
    const float* g0   = (const float*)d_in[8];  const float* be0 = (const float*)d_in[9];
    const float* Wl1  = (const float*)d_in[10]; const float* bl1 = (const float*)d_in[11];
    const float* Wr1  = (const float*)d_in[12]; const float* br1 = (const float*)d_in[13];
    const float* att1 = (const float*)d_in[14]; const float* bo1 = (const float*)d_in[15];
    const float* g1   = (const float*)d_in[16]; const float* be1 = (const float*)d_in[17];
    const float* Wl2  = (const float*)d_in[18]; const float* bl2 = (const float*)d_in[19];
    const float* Wr2  = (const float*)d_in[20]; const float* br2 = (const float*)d_in[21];
    const float* att2 = (const float*)d_in[22]; const float* bo2 = (const float*)d_in[23];
    const float* g2   = (const float*)d_in[24]; const float* be2 = (const float*)d_in[25];
    const float* cW1  = (const float*)d_in[26]; const float* cb1 = (const float*)d_in[27];
    const float* cW2  = (const float*)d_in[28]; const float* cb2 = (const float*)d_in[29];
    float* out = (float*)d_out;

    float *xl, *xr, *ha, *hb, *wc;
    int* cnt;
    cudaGetSymbolAddress((void**)&xl, g_xl);
    cudaGetSymbolAddress((void**)&xr, g_xr);
    cudaGetSymbolAddress((void**)&ha, g_ha);
    cudaGetSymbolAddress((void**)&hb, g_hb);
    cudaGetSymbolAddress((void**)&wc, g_wcat);
    cudaGetSymbolAddress((void**)&cnt, g_cnt);

    const int EB = (ET + 255) / 256;        // thread-per-edge blocks
    const int NW = (NN + 7) / 8;            // warp-per-node blocks (256 thr = 8 warps)
    const int RB = (NN + 127) / 128;        // 128-row GEMM blocks

    // weight repack + CSR build (independent)
    k_repack<<<(49152 + 255) / 256, 256>>>(Wl0, Wr0, Wl1, Wr1, Wl2, Wr2);
    cudaMemsetAsync(cnt, 0, NN * sizeof(int));
    k_scatter_pad<<<EB, 256>>>(ei);

    // ---- layer 0 ----  (KREAL=18 padded to 24 k; Wcat L0 has 32 zero-padded rows)
    k_linm<18, 24, 256, 128><<<dim3(RB, 4), 256>>>(x, wc + OFF_WC0, bl0, br0, xl, xr, NN);
    k_gat128<false><<<NW, 256>>>(xl, xr, att0, bo0, g0, be0, (const float*)0, ha);

    // ---- layer 1 (residual) ----
    k_linm<128, 128, 256, 128><<<dim3(RB, 4), 256>>>(ha, wc + OFF_WC1, bl1, br1, xl, xr, NN);
    k_gat128<true><<<NW, 256>>>(xl, xr, att1, bo1, g1, be1, ha, hb);

    // ---- layer 2 (H=1, D=32) + classifier MLP ----
    k_linm<128, 128, 64, 32><<<dim3(RB, 1), 256>>>(hb, wc + OFF_WC2, bl2, br2, xl, xr, NN);
    k_gat_final<<<NW, 256>>>(xl, xr, att2, bo2, g2, be2, cW1, cb1, cW2, cb2, out);
}

// round 13
// speedup vs baseline: 1.1664x; 1.1664x over previous
#include <cuda_runtime.h>

#define NN 50000
#define EE 800000
#define ET 850000   // EE + NN self loops
#define CAP 96      // padded adjacency capacity (deg ~ Poisson(16)+1; P(>95) ~ 0)

// ---------------- scratch (static device globals; no allocation) ----------------
__device__ __align__(16) float g_xl[NN * 128];
__device__ __align__(16) float g_xr[NN * 128];
__device__ __align__(16) float g_ha[NN * 128];
__device__ __align__(16) float g_hb[NN * 128];
__device__ int   g_cnt[NN];          // per-node cursor / degree
__device__ int   g_adj[NN * CAP];    // padded adjacency (src lists by dst)
// concatenated padded weights: L0 [32][256] @0, L1 [128][256] @8192, L2 [128][64] @40960
__device__ __align__(16) float g_wcat[49152];

#define OFF_WC0 0
#define OFF_WC1 8192
#define OFF_WC2 40960

// ---------------- weight repack: Wcat = [Wl | Wr], K zero-padded ----------------
__global__ void k_repack(const float* __restrict__ W0l, const float* __restrict__ W0r,
                         const float* __restrict__ W1l, const float* __restrict__ W1r,
                         const float* __restrict__ W2l, const float* __restrict__ W2r) {
    int i = blockIdx.x * blockDim.x + threadIdx.x;
    if (i >= 49152) return;
    float v = 0.f;
    if (i < 8192) {                       // L0: KPAD=32, MCAT=256, KREAL=18
        int k = i >> 8, c = i & 255;
        if (k < 18) v = (c < 128) ? W0l[k * 128 + c] : W0r[k * 128 + (c - 128)];
        g_wcat[OFF_WC0 + i] = v;
    } else if (i < 40960) {               // L1: K=128, MCAT=256
        int j = i - 8192;
        int k = j >> 8, c = j & 255;
        v = (c < 128) ? W1l[k * 128 + c] : W1r[k * 128 + (c - 128)];
        g_wcat[i] = v;
    } else {                              // L2: K=128, MCAT=64
        int j = i - 40960;
        int k = j >> 6, c = j & 63;
        v = (c < 32) ? W2l[k * 32 + c] : W2r[k * 32 + (c - 32)];
        g_wcat[i] = v;
    }
}

// ---------------- padded CSR build (by dst): memset + single scatter ----------------
__global__ void k_scatter_pad(const int* __restrict__ ei) {
    int e = blockIdx.x * blockDim.x + threadIdx.x;
    if (e >= ET) return;
    int src, dst;
    if (e < EE) { src = ei[e]; dst = ei[EE + e]; }
    else        { src = e - EE; dst = e - EE; }
    int pos = atomicAdd(&g_cnt[dst], 1);
    if (pos < CAP) g_adj[dst * CAP + pos] = src;
}

// ---------------- raw tf32 mma helpers ----------------
__device__ __forceinline__ unsigned f2tf(float v) {
    unsigned u; asm("cvt.rna.tf32.f32 %0, %1;" : "=r"(u) : "f"(v)); return u;
}
__device__ __forceinline__ void mma_tf32(float* c, const unsigned* a, const unsigned* b) {
    asm("mma.sync.aligned.m16n8k8.row.col.f32.tf32.tf32.f32 "
        "{%0,%1,%2,%3},{%4,%5,%6,%7},{%8,%9},{%0,%1,%2,%3};"
        : "+f"(c[0]), "+f"(c[1]), "+f"(c[2]), "+f"(c[3])
        : "r"(a[0]), "r"(a[1]), "r"(a[2]), "r"(a[3]), "r"(b[0]), "r"(b[1]));
}

// ---------------- tf32 mma dual GEMM, smem-staged, conflict-free ----------------
// out1[n,MOUT] | out2[n,MOUT] = in[n,KREAL] @ Wcat[KPAD, MCAT] + b1|b2  (MCAT=2*MOUT)
// block = 8 warps (4 row x 2 col), block tile 128 rows x 64 cols, warp tile 32x32.
// A staged 128x32/chunk stride 36 (LDS bank = 4*gid+tig, bijective);
// B staged 32x64/chunk  stride 72 (LDS bank = 8*tig+gid, bijective); tf32 at fill.
template<int KREAL, int KPAD, int MCAT, int MOUT>
__global__ void k_lins(const float* __restrict__ in, const float* __restrict__ W,
                       const float* __restrict__ b1, const float* __restrict__ b2,
                       float* __restrict__ out1, float* __restrict__ out2, int nrows) {
    __shared__ unsigned A_s[128 * 36];   // 18 KB
    __shared__ unsigned B_s[32 * 72];    //  9 KB
    int tid  = threadIdx.x;
    int lane = tid & 31;
    int wid  = tid >> 5;
    int gid  = lane >> 2;      // group id 0..7
    int tig  = lane & 3;       // thread in group 0..3
    int wcol = wid & 1, wrow = wid >> 1;
    int row0 = blockIdx.x * 128;
    int colb = blockIdx.y * 64;

    float acc[2][4][4];
#pragma unroll
    for (int mi = 0; mi < 2; mi++)
#pragma unroll
        for (int ni = 0; ni < 4; ni++)
#pragma unroll
            for (int q = 0; q < 4; q++) acc[mi][ni][q] = 0.f;

    for (int kc = 0; kc < KPAD; kc += 32) {
        // ---- stage A chunk (128 x 32) coalesced, tf32-converted ----
        if ((KREAL & 3) == 0) {
            for (int q = tid; q < 1024; q += 256) {
                int r = q >> 3, c4 = (q & 7) << 2;
                int gr = row0 + r;
                float4 v = (gr < nrows)
                    ? __ldg((const float4*)(in + (long)gr * KREAL + kc + c4))
                    : make_float4(0.f, 0.f, 0.f, 0.f);
                uint4 u = make_uint4(f2tf(v.x), f2tf(v.y), f2tf(v.z), f2tf(v.w));
                *(uint4*)(A_s + r * 36 + c4) = u;
            }
        } else {
            for (int q = tid; q < 4096; q += 256) {
                int r = q >> 5, c = q & 31;
                int gr = row0 + r, gc = kc + c;
                float v = (gr < nrows && gc < KREAL) ? __ldg(in + (long)gr * KREAL + gc) : 0.f;
                A_s[r * 36 + c] = f2tf(v);
            }
        }
        // ---- stage B chunk (32 x 64) coalesced (Wcat pre-padded) ----
        for (int q = tid; q < 512; q += 256) {
            int r = q >> 4, c4 = (q & 15) << 2;
            float4 v = __ldg((const float4*)(W + (long)(kc + r) * MCAT + colb + c4));
            uint4 u = make_uint4(f2tf(v.x), f2tf(v.y), f2tf(v.z), f2tf(v.w));
            *(uint4*)(B_s + r * 72 + c4) = u;
        }
        __syncthreads();

#pragma unroll
        for (int ks = 0; ks < 4; ks++) {
            int kk = ks * 8;
            unsigned A[2][4], B[4][2];
#pragma unroll
            for (int mi = 0; mi < 2; mi++) {
                int lr = wrow * 32 + mi * 16 + gid;
                A[mi][0] = A_s[lr * 36 + kk + tig];
                A[mi][1] = A_s[(lr + 8) * 36 + kk + tig];
                A[mi][2] = A_s[lr * 36 + kk + tig + 4];
                A[mi][3] = A_s[(lr + 8) * 36 + kk + tig + 4];
            }
#pragma unroll
            for (int ni = 0; ni < 4; ni++) {
                int bn = wcol * 32 + ni * 8 + gid;
                B[ni][0] = B_s[(kk + tig) * 72 + bn];
                B[ni][1] = B_s[(kk + tig + 4) * 72 + bn];
            }
#pragma unroll
            for (int mi = 0; mi < 2; mi++)
#pragma unroll
                for (int ni = 0; ni < 4; ni++)
                    mma_tf32(acc[mi][ni], A[mi], B[ni]);
        }
        __syncthreads();
    }

    // ---- epilogue: bias + route to out1/out2 (same fragment->matrix map as before) ----
#pragma unroll
    for (int mi = 0; mi < 2; mi++) {
        int rowm = row0 + wrow * 32 + mi * 16 + gid;
#pragma unroll
        for (int ni = 0; ni < 4; ni++) {
            int col = colb + wcol * 32 + ni * 8 + tig * 2;
#pragma unroll
            for (int h = 0; h < 2; h++) {
                int row = rowm + h * 8;
                if (row >= nrows) continue;
                float vx = acc[mi][ni][h * 2], vy = acc[mi][ni][h * 2 + 1];
                if (col < MOUT) {
                    float2 bb = *(const float2*)(b1 + col);
                    *(float2*)(out1 + (long)row * MOUT + col) =
                        make_float2(vx + bb.x, vy + bb.y);
                } else {
                    float2 bb = *(const float2*)(b2 + col - MOUT);
                    *(float2*)(out2 + (long)row * MOUT + col - MOUT) =
                        make_float2(vx + bb.x, vy + bb.y);
                }
            }
        }
    }
}

// ---------------- warp helpers ----------------
__device__ __forceinline__ float warp_sum(float v) {
#pragma unroll
    for (int o = 16; o > 0; o >>= 1) v += __shfl_xor_sync(0xffffffffu, v, o);
    return v;
}

// ---------------- fused GATv2 layer (HD=128, H=4) — R11 rolling-prefetch version ----
template<bool RES>
__global__ void __launch_bounds__(256, 6)
k_gat128(const float* __restrict__ xl, const float* __restrict__ xr,
         const float* __restrict__ att,
         const float* __restrict__ bo, const float* __restrict__ gg,
         const float* __restrict__ be, const float* __restrict__ resid,
         float* __restrict__ out) {
    int node = (blockIdx.x * blockDim.x + threadIdx.x) >> 5;
    int lane = threadIdx.x & 31;
    if (node >= NN) return;
    int deg = g_cnt[node];
    const int* adj = g_adj + (long)node * CAP;

    float4 xr4 = *(const float4*)(xr + (long)node * 128 + (lane << 2));
    float4 at4 = __ldg((const float4*)(att + (lane << 2)));

    float den = 0.f;
    float ax = 0.f, ay = 0.f, az = 0.f, aw = 0.f;

    for (int base = 0; base < deg; base += 32) {
        int rem = deg - base;
        int n = rem > 32 ? 32 : rem;
        int s = adj[base + ((lane < n) ? lane : 0)];
        int s0 = __shfl_sync(0xffffffffu, s, 0);
        int s1 = __shfl_sync(0xffffffffu, s, (n > 1) ? 1 : 0);
        float4 v0 = *(const float4*)(xl + (long)s0 * 128 + (lane << 2));
        float4 v1 = *(const float4*)(xl + (long)s1 * 128 + (lane << 2));
#pragma unroll 4
        for (int j = 0; j < n; j++) {
            float4 vc = v0;
            v0 = v1;
            int j2 = j + 2; j2 = (j2 < n) ? j2 : (n - 1);
            int sn = __shfl_sync(0xffffffffu, s, j2);
            v1 = *(const float4*)(xl + (long)sn * 128 + (lane << 2));

            float t0 = vc.x + xr4.x; t0 = fmaxf(t0, 0.2f * t0);
            float t1 = vc.y + xr4.y; t1 = fmaxf(t1, 0.2f * t1);
            float t2 = vc.z + xr4.z; t2 = fmaxf(t2, 0.2f * t2);
            float t3 = vc.w + xr4.w; t3 = fmaxf(t3, 0.2f * t3);
            float p = fmaf(t0, at4.x, fmaf(t1, at4.y, fmaf(t2, at4.z, t3 * at4.w)));
            p += __shfl_xor_sync(0xffffffffu, p, 1);
            p += __shfl_xor_sync(0xffffffffu, p, 2);
            p += __shfl_xor_sync(0xffffffffu, p, 4);
            float a = __expf(fminf(p, 60.f));
            ax = fmaf(a, vc.x, ax); ay = fmaf(a, vc.y, ay);
            az = fmaf(a, vc.z, az); aw = fmaf(a, vc.w, aw);
            den += a;
        }
    }

    float inv = 1.f / den;
    float4 bo4 = __ldg((const float4*)(bo + (lane << 2)));
    float o0 = ax * inv + bo4.x;
    float o1 = ay * inv + bo4.y;
    float o2 = az * inv + bo4.z;
    float o3 = aw * inv + bo4.w;

    float mean = warp_sum(o0 + o1 + o2 + o3) * (1.f / 128.f);
    float e0 = o0 - mean, e1 = o1 - mean, e2 = o2 - mean, e3 = o3 - mean;
    float var = warp_sum(e0 * e0 + e1 * e1 + e2 * e2 + e3 * e3) * (1.f / 128.f);
    float rinv = rsqrtf(var + 1e-5f);
    float4 g4  = __ldg((const float4*)(gg + (lane << 2)));
    float4 be4 = __ldg((const float4*)(be + (lane << 2)));
    float v0 = e0 * rinv * g4.x + be4.x;
    float v1 = e1 * rinv * g4.y + be4.y;
    float v2 = e2 * rinv * g4.z + be4.z;
    float v3 = e3 * rinv * g4.w + be4.w;
    v0 = (v0 > 0.f) ? v0 : (__expf(v0) - 1.f);
    v1 = (v1 > 0.f) ? v1 : (__expf(v1) - 1.f);
    v2 = (v2 > 0.f) ? v2 : (__expf(v2) - 1.f);
    v3 = (v3 > 0.f) ? v3 : (__expf(v3) - 1.f);
    if (RES) {
        float4 r4 = *(const float4*)(resid + (long)node * 128 + (lane << 2));
        v0 += r4.x; v1 += r4.y; v2 += r4.z; v3 += r4.w;
    }
    *(float4*)(out + (long)node * 128 + (lane << 2)) = make_float4(v0, v1, v2, v3);
}

// ---------------- layer-2 (HD=32, H=1) fused with final MLP ----------------
__global__ void __launch_bounds__(256, 6)
k_gat_final(const float* __restrict__ xl, const float* __restrict__ xr,
            const float* __restrict__ att,
            const float* __restrict__ bo, const float* __restrict__ gg,
            const float* __restrict__ be,
            const float* __restrict__ cW1, const float* __restrict__ cb1,
            const float* __restrict__ cW2, const float* __restrict__ cb2,
            float* __restrict__ out) {
    __shared__ float sh[8][32];
    int node = (blockIdx.x * blockDim.x + threadIdx.x) >> 5;
    int lane = threadIdx.x & 31;
    int wib  = threadIdx.x >> 5;
    if (node >= NN) return;
    int deg = g_cnt[node];
    const int* adj = g_adj + (long)node * CAP;

    float xrv = xr[(long)node * 32 + lane];
    float atv = __ldg(&att[lane]);

    float den = 0.f, acc = 0.f;
    for (int base = 0; base < deg; base += 32) {
        int rem = deg - base;
        int n = rem > 32 ? 32 : rem;
        int s = adj[base + ((lane < n) ? lane : 0)];
        int s0 = __shfl_sync(0xffffffffu, s, 0);
        int s1 = __shfl_sync(0xffffffffu, s, (n > 1) ? 1 : 0);
        float v0 = xl[(long)s0 * 32 + lane];
        float v1 = xl[(long)s1 * 32 + lane];
#pragma unroll 4
        for (int j = 0; j < n; j++) {
            float vc = v0;
            v0 = v1;
            int j2 = j + 2; j2 = (j2 < n) ? j2 : (n - 1);
            int sn = __shfl_sync(0xffffffffu, s, j2);
            v1 = xl[(long)sn * 32 + lane];

            float t = vc + xrv; t = fmaxf(t, 0.2f * t);
            float p = warp_sum(t * atv);
            float a = __expf(fminf(p, 60.f));
            acc = fmaf(a, vc, acc);
            den += a;
        }
    }
    float o = acc / den + bo[lane];

    float mean = warp_sum(o) * (1.f / 32.f);
    float ec = o - mean;
    float var = warp_sum(ec * ec) * (1.f / 32.f);
    float v = ec * rsqrtf(var + 1e-5f) * gg[lane] + be[lane];
    v = (v > 0.f) ? v : (__expf(v) - 1.f);   // ELU

    sh[wib][lane] = v;
    __syncwarp();

    float r = 0.f;
    if (lane < 16) {
        float c = cb1[lane];
#pragma unroll
        for (int j = 0; j < 32; j++) c += sh[wib][j] * cW1[j * 16 + lane];
        c = (c > 0.f) ? c : (__expf(c) - 1.f);   // ELU
        r = c * cW2[lane];
    }
#pragma unroll
    for (int o2 = 8; o2 > 0; o2 >>= 1) r += __shfl_xor_sync(0xffffffffu, r, o2);
    if (lane == 0) out[node] = r + cb2[0];
}

// ---------------- host ----------------
extern "C" void kernel_launch(void* const* d_in, const int* in_sizes, int n_in,
                              void* d_out, int out_size) {
    const float* x    = (const float*)d_in[0];
    const int*   ei   = (const int*)  d_in[1];
    const float* Wl0  = (const float*)d_in[2];  const float* bl0 = (const float*)d_in[3];
    const float* Wr0  = (const float*)d_in[4];  const float* br0 = (const float*)d_in[5];
    const float* att0 = (const float*)d_in[6];  const float* bo0 = (const float*)d_in[7];
    const float* g0   = (const float*)d_in[8];  const float* be0 = (const float*)d_in[9];
    const float* Wl1  = (const float*)d_in[10]; const float* bl1 = (const float*)d_in[11];
    const float* Wr1  = (const float*)d_in[12]; const float* br1 = (const float*)d_in[13];
    const float* att1 = (const float*)d_in[14]; const float* bo1 = (const float*)d_in[15];
    const float* g1   = (const float*)d_in[16]; const float* be1 = (const float*)d_in[17];
    const float* Wl2  = (const float*)d_in[18]; const float* bl2 = (const float*)d_in[19];
    const float* Wr2  = (const float*)d_in[20]; const float* br2 = (const float*)d_in[21];
    const float* att2 = (const float*)d_in[22]; const float* bo2 = (const float*)d_in[23];
    const float* g2   = (const float*)d_in[24]; const float* be2 = (const float*)d_in[25];
    const float* cW1  = (const float*)d_in[26]; const float* cb1 = (const float*)d_in[27];
    const float* cW2  = (const float*)d_in[28]; const float* cb2 = (const float*)d_in[29];
    float* out = (float*)d_out;

    float *xl, *xr, *ha, *hb, *wc;
    int* cnt;
    cudaGetSymbolAddress((void**)&xl, g_xl);
    cudaGetSymbolAddress((void**)&xr, g_xr);
    cudaGetSymbolAddress((void**)&ha, g_ha);
    cudaGetSymbolAddress((void**)&hb, g_hb);
    cudaGetSymbolAddress((void**)&wc, g_wcat);
    cudaGetSymbolAddress((void**)&cnt, g_cnt);

    const int EB = (ET + 255) / 256;        // thread-per-edge blocks
    const int NW = (NN + 7) / 8;            // warp-per-node blocks (256 thr = 8 warps)
    const int RB = (NN + 127) / 128;        // 128-row GEMM blocks

    // weight repack + CSR build (independent)
    k_repack<<<(49152 + 255) / 256, 256>>>(Wl0, Wr0, Wl1, Wr1, Wl2, Wr2);
    cudaMemsetAsync(cnt, 0, NN * sizeof(int));
    k_scatter_pad<<<EB, 256>>>(ei);

    // ---- layer 0 ----  (KREAL=18, KPAD=32: one zero-padded 32-chunk)
    k_lins<18, 32, 256, 128><<<dim3(RB, 4), 256>>>(x, wc + OFF_WC0, bl0, br0, xl, xr, NN);
    k_gat128<false><<<NW, 256>>>(xl, xr, att0, bo0, g0, be0, (const float*)0, ha);

    // ---- layer 1 (residual) ----
    k_lins<128, 128, 256, 128><<<dim3(RB, 4), 256>>>(ha, wc + OFF_WC1, bl1, br1, xl, xr, NN);
    k_gat128<true><<<NW, 256>>>(xl, xr, att1, bo1, g1, be1, ha, hb);

    // ---- layer 2 (H=1, D=32) + classifier MLP ----
    k_lins<128, 128, 64, 32><<<dim3(RB, 1), 256>>>(hb, wc + OFF_WC2, bl2, br2, xl, xr, NN);
    k_gat_final<<<NW, 256>>>(xl, xr, att2, bo2, g2, be2, cW1, cb1, cW2, cb2, out);
}